// round 16
// baseline (speedup 1.0000x reference)
#include <cuda_runtime.h>
#include <cuda_fp16.h>
#include <math.h>
#include <stdint.h>

// Problem constants
#define BATCH 2
#define TSEQ  4096
#define DIM   2048
#define NH    16
#define HD    128
#define M1    (BATCH*TSEQ)      // 8192
#define N_QKV (3*DIM)           // 6144

// ---------------- scratch (static device globals; no allocs allowed) ----------
__device__ __half g_xh[(size_t)M1 * DIM];
__device__ __half g_wqkvh[(size_t)N_QKV * DIM];
__device__ __half g_wprojh[(size_t)DIM * DIM];
__device__ __half g_qh[(size_t)BATCH*NH*TSEQ*HD];      // [bh][t][d]
__device__ __half g_kh[(size_t)BATCH*NH*TSEQ*HD];      // [bh][t][d]
__device__ __half g_vh[(size_t)BATCH*NH*TSEQ*HD];      // [bh][t][d]
__device__ __half g_vth[(size_t)BATCH*NH*HD*TSEQ];     // [bh][d][t]  (transposed)
__device__ __half g_atth[(size_t)M1 * DIM];
__device__ float  g_ctab[(size_t)TSEQ * HD];
__device__ float  g_stab[(size_t)TSEQ * HD];

// ---------------- helpers -----------------------------------------------------
__device__ __forceinline__ void mma_f16(float* d, const uint32_t* a, const uint32_t* b) {
    asm volatile(
        "mma.sync.aligned.m16n8k16.row.col.f32.f16.f16.f32 "
        "{%0,%1,%2,%3}, {%4,%5,%6,%7}, {%8,%9}, {%0,%1,%2,%3};"
        : "+f"(d[0]), "+f"(d[1]), "+f"(d[2]), "+f"(d[3])
        : "r"(a[0]), "r"(a[1]), "r"(a[2]), "r"(a[3]), "r"(b[0]), "r"(b[1]));
}

__device__ __forceinline__ void ldsm_x4(uint32_t* r, uint32_t saddr) {
    asm volatile("ldmatrix.sync.aligned.m8n8.x4.shared.b16 {%0,%1,%2,%3}, [%4];"
        : "=r"(r[0]), "=r"(r[1]), "=r"(r[2]), "=r"(r[3]) : "r"(saddr));
}

__device__ __forceinline__ uint32_t smem_u32(const void* p) {
    uint32_t a;
    asm("{ .reg .u64 t; cvta.to.shared.u64 t, %1; cvt.u32.u64 %0, t; }" : "=r"(a) : "l"(p));
    return a;
}
__device__ __forceinline__ void cp_async16(uint32_t saddr, const void* gaddr) {
    asm volatile("cp.async.cg.shared.global [%0], [%1], 16;" :: "r"(saddr), "l"(gaddr));
}
#define CP_COMMIT() asm volatile("cp.async.commit_group;" ::: "memory")
#define CP_WAIT1()  asm volatile("cp.async.wait_group 1;" ::: "memory")
#define CP_WAIT2()  asm volatile("cp.async.wait_group 2;" ::: "memory")

__device__ __forceinline__ uint32_t h2u(__half2 h) {
    union { __half2 h; uint32_t u; } c; c.h = h; return c.u;
}

// ---------------- cos/sin table ----------------------------------------------
__global__ void build_tab(float* __restrict__ ct, float* __restrict__ st) {
    int t = blockIdx.x;
    int j = threadIdx.x;
    int m = j & 63;
    float base = (float)pow(10000.0, (double)m / 64.0);
    float invf = 1.0f / base;
    float ang = (float)t * invf;
    ct[t*HD + j] = cosf(ang);
    st[t*HD + j] = sinf(ang);
}

// ---------------- fp32 -> fp16 pass (8 elems/thread) --------------------------
__global__ void round_half(const float* __restrict__ in, __half* __restrict__ out) {
    size_t i = ((size_t)blockIdx.x * 256 + threadIdx.x) * 8;
    float4 v0 = *(const float4*)(in + i);
    float4 v1 = *(const float4*)(in + i + 4);
    uint4 u;
    u.x = h2u(__floats2half2_rn(v0.x, v0.y));
    u.y = h2u(__floats2half2_rn(v0.z, v0.w));
    u.z = h2u(__floats2half2_rn(v1.x, v1.y));
    u.w = h2u(__floats2half2_rn(v1.z, v1.w));
    *(uint4*)(out + i) = u;
}

// ---------------- GEMM core (shared by both kernels) --------------------------
// 128x128 CTA tile, 4 warps (2x2) of 64x64, BK=32, 4 stages, 128 threads.
#define BM 128
#define BN 128
#define BKH 32
#define STAGES 4
#define HSTR 40
#define GEMMH_SMEM (STAGES * (BM + BN) * HSTR * 2)    // 81920 B

struct GemmCtx {
    int tid, lane, g, tg, wm, wn, m0, n0;
    int la_row, la_k, lb_row, lb_k;
    uint32_t sbase, boff;
};

__device__ __forceinline__ void gemm_core(
    const __half* __restrict__ A, const __half* __restrict__ B,
    int K, GemmCtx& cx, float acc[4][8][4])
{
#pragma unroll
    for (int i = 0; i < 4; i++)
#pragma unroll
        for (int j = 0; j < 8; j++)
#pragma unroll
            for (int r = 0; r < 4; r++) acc[i][j][r] = 0.f;

    const int nch = K / BKH;

    auto issue = [&](int ch, bool pred) {
        if (pred) {
            int s = ch % STAGES;
            const __half* Ag = A + (size_t)cx.m0 * K + ch * BKH;
            const __half* Bg = B + (size_t)cx.n0 * K + ch * BKH;
            uint32_t as = cx.sbase + (uint32_t)(s * BM * HSTR) * 2u;
            uint32_t bs = cx.sbase + (cx.boff + (uint32_t)(s * BN * HSTR)) * 2u;
#pragma unroll
            for (int e = 0; e < 4; e++) {
                int idx = cx.tid + e * 128;
                int r  = idx >> 2;
                int c8 = (idx & 3) << 3;
                cp_async16(as + (uint32_t)(r * HSTR + c8) * 2u, Ag + (size_t)r * K + c8);
                cp_async16(bs + (uint32_t)(r * HSTR + c8) * 2u, Bg + (size_t)r * K + c8);
            }
        }
        CP_COMMIT();
    };

    issue(0, true);
    issue(1, 1 < nch);
    issue(2, 2 < nch);

    for (int ch = 0; ch < nch; ch++) {
        CP_WAIT2();
        __syncthreads();
        issue(ch + 3, ch + 3 < nch);

        int s = ch % STAGES;
        uint32_t asad = cx.sbase + (uint32_t)(s * BM * HSTR) * 2u;
        uint32_t bsad = cx.sbase + (cx.boff + (uint32_t)(s * BN * HSTR)) * 2u;

#pragma unroll
        for (int ks = 0; ks < BKH; ks += 16) {
            uint32_t afr[4][4];
#pragma unroll
            for (int mi = 0; mi < 4; mi++) {
                int mr = cx.wm * 64 + mi * 16;
                ldsm_x4(afr[mi], asad + (uint32_t)((mr + cx.la_row) * HSTR + ks + cx.la_k) * 2u);
            }
            uint32_t bfr[8][2];
#pragma unroll
            for (int p = 0; p < 4; p++) {
                int nr2 = cx.wn * 64 + p * 16;
                uint32_t r4[4];
                ldsm_x4(r4, bsad + (uint32_t)((nr2 + cx.lb_row) * HSTR + ks + cx.lb_k) * 2u);
                bfr[2*p  ][0] = r4[0]; bfr[2*p  ][1] = r4[1];
                bfr[2*p+1][0] = r4[2]; bfr[2*p+1][1] = r4[3];
            }
#pragma unroll
            for (int mi = 0; mi < 4; mi++)
#pragma unroll
                for (int nj = 0; nj < 8; nj++)
                    mma_f16(acc[mi][nj], afr[mi], bfr[nj]);
        }
    }
}

__device__ __forceinline__ void gemm_init_ctx(GemmCtx& cx, uint32_t sbase) {
    cx.tid  = threadIdx.x;
    int wid = cx.tid >> 5;
    cx.lane = cx.tid & 31;
    cx.g    = cx.lane >> 2;
    cx.tg   = cx.lane & 3;
    cx.wm   = wid >> 1;
    cx.wn   = wid & 1;
    cx.m0   = blockIdx.y * BM;
    cx.n0   = blockIdx.x * BN;
    cx.la_row = cx.lane & 15;
    cx.la_k   = (cx.lane >> 4) << 3;
    cx.lb_row = ((cx.lane >> 4) << 3) + (cx.lane & 7);
    cx.lb_k   = ((cx.lane >> 3) & 1) << 3;
    cx.sbase  = sbase;
    cx.boff   = STAGES * BM * HSTR;
}

// ---------------- QKV GEMM with fused RoPE epilogue ---------------------------
__global__ __launch_bounds__(128, 2) void gemm_qkv(
    const __half* __restrict__ A, const __half* __restrict__ B,
    const float* __restrict__ ct, const float* __restrict__ st,
    __half* __restrict__ Qh, __half* __restrict__ Kh, __half* __restrict__ Vh)
{
    extern __shared__ __half hsm[];
    GemmCtx cx;
    gemm_init_ctx(cx, smem_u32(hsm));

    float acc[4][8][4];
    gemm_core(A, B, DIM, cx, acc);

    int region = cx.n0 >> 11;          // 0=Q, 1=K, 2=V (CTA-uniform)
    __half* dst = (region == 0) ? Qh : ((region == 1) ? Kh : Vh);

#pragma unroll
    for (int mi = 0; mi < 4; mi++) {
#pragma unroll
        for (int nj = 0; nj < 8; nj++) {
            int row = cx.m0 + cx.wm * 64 + mi * 16 + cx.g;
            int col = cx.n0 + cx.wn * 64 + nj * 8 + cx.tg * 2;
            int hcol = col & 2047;
            int h = hcol >> 7, j = hcol & 127;
            int b = row >> 12, t = row & (TSEQ - 1);
            size_t ob0 = ((size_t)((b << 4) + h) * TSEQ + t) * HD + j;
            size_t ob1 = ob0 + 8 * HD;     // row+8 -> t+8 (same b)
            float x0 = acc[mi][nj][0], x1 = acc[mi][nj][1];
            float y0 = acc[mi][nj][2], y1 = acc[mi][nj][3];
            if (region < 2) {
                float2 c0 = *(const float2*)(ct + t*HD + j);
                float2 s0 = *(const float2*)(st + t*HD + j);
                float2 c1 = *(const float2*)(ct + (t+8)*HD + j);
                float2 s1 = *(const float2*)(st + (t+8)*HD + j);
                *(__half2*)(dst + ob0) =
                    __floats2half2_rn(x0 * c0.x - x1 * s0.x, x1 * c0.y + x0 * s0.y);
                *(__half2*)(dst + ob1) =
                    __floats2half2_rn(y0 * c1.x - y1 * s1.x, y1 * c1.y + y0 * s1.y);
            } else {
                *(__half2*)(dst + ob0) = __floats2half2_rn(x0, x1);
                *(__half2*)(dst + ob1) = __floats2half2_rn(y0, y1);
            }
        }
    }
}

// ---------------- Projection GEMM (fp32 out) ----------------------------------
__global__ __launch_bounds__(128, 2) void gemm_h(
    const __half* __restrict__ A, const __half* __restrict__ B,
    float* __restrict__ C, int N, int K)
{
    extern __shared__ __half hsm[];
    GemmCtx cx;
    gemm_init_ctx(cx, smem_u32(hsm));

    float acc[4][8][4];
    gemm_core(A, B, K, cx, acc);

#pragma unroll
    for (int mi = 0; mi < 4; mi++) {
#pragma unroll
        for (int nj = 0; nj < 8; nj++) {
            int row = cx.m0 + cx.wm * 64 + mi * 16 + cx.g;
            int col = cx.n0 + cx.wn * 64 + nj * 8 + cx.tg * 2;
            *(float2*)(C + (size_t)row * N + col) =
                make_float2(acc[mi][nj][0], acc[mi][nj][1]);
            *(float2*)(C + (size_t)(row + 8) * N + col) =
                make_float2(acc[mi][nj][2], acc[mi][nj][3]);
        }
    }
}

// ---------------- V transpose: Vh[bh][t][d] -> Vt[bh][d][t] (half) -----------
__global__ void vtrans(const __half* __restrict__ Vh, __half* __restrict__ Vt) {
    __shared__ __half tile[32][34];
    int bh = blockIdx.z;
    int t0 = blockIdx.x * 32;
    int d0 = blockIdx.y * 32;
    int tx = threadIdx.x, ty = threadIdx.y;   // 32 x 8

#pragma unroll
    for (int i = 0; i < 4; i++) {
        int t = t0 + ty + i * 8;
        tile[ty + i*8][tx] = Vh[((size_t)bh * TSEQ + t) * HD + d0 + tx];
    }
    __syncthreads();
#pragma unroll
    for (int i = 0; i < 4; i++) {
        int d = d0 + ty + i * 8;
        Vt[((size_t)bh * HD + d) * TSEQ + t0 + tx] = tile[tx][ty + i*8];
    }
}

// ---------------- fp16 mma flash attention (causal, FK=128) ------------------
// Q tile 128, K tile 128, 8 warps; warp = 16 Q rows x full K width.
#define FQ 128
#define FK 128
#define QSTR 136       // halves
#define KSTR 136
#define VSTR 136
#define PSTR 136
#define OFF_Q  0
#define OFF_K0 (OFF_Q  + FQ*QSTR)     // 17408
#define OFF_K1 (OFF_K0 + FK*KSTR)     // 34816
#define OFF_V  (OFF_K1 + FK*KSTR)     // 52224
#define OFF_P  (OFF_V  + HD*VSTR)     // 69632
#define FLASHH_HALVES (OFF_P + FQ*PSTR)   // 87040
#define FLASHH_BYTES (FLASHH_HALVES * 2)  // 174080

__global__ __launch_bounds__(256, 1) void flash_h(
    const __half* __restrict__ Q, const __half* __restrict__ K,
    const __half* __restrict__ Vt, __half* __restrict__ Oatt)
{
    extern __shared__ __half hs[];
    __half* Ps = hs + OFF_P;
    uint32_t sbase = smem_u32(hs);

    int qi  = blockIdx.x;
    int bh  = blockIdx.y;
    int tid = threadIdx.x;
    int w    = tid >> 5;
    int lane = tid & 31;
    int g    = lane >> 2;
    int tg   = lane & 3;

    int la_row = lane & 15;
    int la_k   = (lane >> 4) << 3;
    int lb_row = ((lane >> 4) << 3) + (lane & 7);
    int lb_k   = ((lane >> 3) & 1) << 3;

    const __half* Qp  = Q  + (size_t)bh * TSEQ * HD;
    const __half* Kp  = K  + (size_t)bh * TSEQ * HD;
    const __half* Vtp = Vt + (size_t)bh * HD * TSEQ;

    int q0 = qi * FQ;
    int nkt = qi + 1;

    auto issueK = [&](int kt, bool pred) {
        if (pred) {
            int k0 = kt * FK;
            uint32_t kb = sbase + (uint32_t)((kt & 1) ? OFF_K1 : OFF_K0) * 2u;
#pragma unroll
            for (int e = 0; e < 8; e++) {
                int idx = tid + e * 256;
                int r  = idx >> 4;
                int c8 = (idx & 15) << 3;
                cp_async16(kb + (uint32_t)(r * KSTR + c8) * 2u,
                           Kp + (size_t)(k0 + r) * HD + c8);
            }
        }
        CP_COMMIT();
    };
    auto issueV = [&](int kt) {
        int k0 = kt * FK;
        uint32_t vb = sbase + (uint32_t)OFF_V * 2u;
#pragma unroll
        for (int e = 0; e < 8; e++) {
            int idx = tid + e * 256;
            int d  = idx >> 4;
            int c8 = (idx & 15) << 3;
            cp_async16(vb + (uint32_t)(d * VSTR + c8) * 2u,
                       Vtp + (size_t)d * TSEQ + k0 + c8);
        }
        CP_COMMIT();
    };

    issueK(0, true);

    // load Q tile
#pragma unroll
    for (int e = 0; e < 8; e++) {
        int idx = tid + e * 256;
        int r  = idx >> 4;
        int c8 = (idx & 15) << 3;
        uint4 v = *(const uint4*)(Qp + (size_t)(q0 + r) * HD + c8);
        *(uint4*)(hs + OFF_Q + r * QSTR + c8) = v;
    }

    float o[16][4];
#pragma unroll
    for (int i = 0; i < 16; i++)
#pragma unroll
        for (int j = 0; j < 4; j++) o[i][j] = 0.f;

    float m0r = -1e30f, m1r = -1e30f;
    float l0 = 0.f, l1 = 0.f;
    const float scale = 0.08838834764831845f;   // 1/sqrt(128)

    int rowbase = q0 + w * 16;
    int r0g = rowbase + g;
    int r1g = rowbase + g + 8;
    int rq = rowbase - q0;

    uint32_t qad   = sbase + (uint32_t)(OFF_Q + (rq + la_row) * QSTR + la_k) * 2u;
    uint32_t pad_a = sbase + (uint32_t)(OFF_P + (rq + la_row) * PSTR + la_k) * 2u;

    float s[16][4];

    for (int kt = 0; kt < nkt; kt++) {
        int k0 = kt * FK;
        uint32_t kad = sbase + (uint32_t)(((kt & 1) ? OFF_K1 : OFF_K0) + lb_row * KSTR + lb_k) * 2u;

        issueV(kt);
        issueK(kt + 1, kt + 1 < nkt);
        CP_WAIT2();                 // K(kt) done; V(kt), K(kt+1) in flight
        __syncthreads();

        // ---- S = Q K^T : 8 ks steps of k=16, 16 column tiles ----
#pragma unroll
        for (int nj = 0; nj < 16; nj++)
#pragma unroll
            for (int r = 0; r < 4; r++) s[nj][r] = 0.f;

#pragma unroll
        for (int ks = 0; ks < 8; ks++) {
            uint32_t a[4];
            ldsm_x4(a, qad + (uint32_t)(ks * 16) * 2u);
            uint32_t bfr[16][2];
#pragma unroll
            for (int p = 0; p < 8; p++) {
                uint32_t r4[4];
                ldsm_x4(r4, kad + (uint32_t)(p * 16 * KSTR + ks * 16) * 2u);
                bfr[2*p  ][0] = r4[0]; bfr[2*p  ][1] = r4[1];
                bfr[2*p+1][0] = r4[2]; bfr[2*p+1][1] = r4[3];
            }
#pragma unroll
            for (int nj = 0; nj < 16; nj++)
                mma_f16(s[nj], a, bfr[nj]);
        }

        // ---- causal mask (only the diagonal tile) ----
        if (k0 + FK - 1 > rowbase) {
#pragma unroll
            for (int nj = 0; nj < 16; nj++) {
                int c = k0 + nj*8 + 2*tg;
                if (c     > r0g) s[nj][0] = -1e30f;
                if (c + 1 > r0g) s[nj][1] = -1e30f;
                if (c     > r1g) s[nj][2] = -1e30f;
                if (c + 1 > r1g) s[nj][3] = -1e30f;
            }
        }

        // ---- online softmax (warp-local, quad reductions) ----
        float mx0 = -1e30f, mx1 = -1e30f;
#pragma unroll
        for (int nj = 0; nj < 16; nj++) {
            mx0 = fmaxf(mx0, fmaxf(s[nj][0], s[nj][1]));
            mx1 = fmaxf(mx1, fmaxf(s[nj][2], s[nj][3]));
        }
        mx0 = fmaxf(mx0, __shfl_xor_sync(0xffffffff, mx0, 1));
        mx0 = fmaxf(mx0, __shfl_xor_sync(0xffffffff, mx0, 2));
        mx1 = fmaxf(mx1, __shfl_xor_sync(0xffffffff, mx1, 1));
        mx1 = fmaxf(mx1, __shfl_xor_sync(0xffffffff, mx1, 2));

        float mn0 = fmaxf(m0r, mx0);
        float mn1 = fmaxf(m1r, mx1);
        float al0 = __expf((m0r - mn0) * scale);
        float al1 = __expf((m1r - mn1) * scale);
        m0r = mn0; m1r = mn1;

        float sum0 = 0.f, sum1 = 0.f;
#pragma unroll
        for (int nj = 0; nj < 16; nj++) {
            float p0 = __expf((s[nj][0] - mn0) * scale);
            float p1 = __expf((s[nj][1] - mn0) * scale);
            float p2 = __expf((s[nj][2] - mn1) * scale);
            float p3 = __expf((s[nj][3] - mn1) * scale);
            s[nj][0] = p0; s[nj][1] = p1; s[nj][2] = p2; s[nj][3] = p3;
            sum0 += p0 + p1; sum1 += p2 + p3;
        }
        sum0 += __shfl_xor_sync(0xffffffff, sum0, 1);
        sum0 += __shfl_xor_sync(0xffffffff, sum0, 2);
        sum1 += __shfl_xor_sync(0xffffffff, sum1, 1);
        sum1 += __shfl_xor_sync(0xffffffff, sum1, 2);

        l0 = l0 * al0 + sum0;
        l1 = l1 * al1 + sum1;

#pragma unroll
        for (int t2 = 0; t2 < 16; t2++) {
            o[t2][0] *= al0; o[t2][1] *= al0;
            o[t2][2] *= al1; o[t2][3] *= al1;
        }

        // ---- write P (half2 pairs) ----
        int pr0 = (rq + g) * PSTR;
        int pr1 = (rq + g + 8) * PSTR;
#pragma unroll
        for (int nj = 0; nj < 16; nj++) {
            int c = nj*8 + 2*tg;
            *(__half2*)(Ps + pr0 + c) = __floats2half2_rn(s[nj][0], s[nj][1]);
            *(__half2*)(Ps + pr1 + c) = __floats2half2_rn(s[nj][2], s[nj][3]);
        }

        CP_WAIT1();                 // V(kt) done; K(kt+1) may be in flight
        __syncthreads();

        // ---- O += P V : 8 ks2 steps of k=16 tokens, 16 d-tiles ----
        uint32_t vad = sbase + (uint32_t)(OFF_V + lb_row * VSTR + lb_k) * 2u;
#pragma unroll
        for (int ks2 = 0; ks2 < 8; ks2++) {
            uint32_t a2[4];
            ldsm_x4(a2, pad_a + (uint32_t)(ks2 * 16) * 2u);
#pragma unroll
            for (int p = 0; p < 8; p++) {
                uint32_t r4[4];
                ldsm_x4(r4, vad + (uint32_t)(p * 16 * VSTR + ks2 * 16) * 2u);
                uint32_t b0[2] = { r4[0], r4[1] };
                uint32_t b1[2] = { r4[2], r4[3] };
                mma_f16(o[2*p  ], a2, b0);
                mma_f16(o[2*p+1], a2, b1);
            }
        }
        __syncthreads();            // V buffer + K stage free for next iter
    }

    // epilogue: normalize + write att as half (proj GEMM A operand)
    float inv0 = 1.0f / l0;
    float inv1 = 1.0f / l1;
    int b = bh >> 4, h = bh & 15;
#pragma unroll
    for (int nj2 = 0; nj2 < 16; nj2++) {
        int col = h * HD + nj2*8 + 2*tg;
        *(__half2*)(Oatt + (size_t)(b*TSEQ + r0g) * DIM + col) =
            __floats2half2_rn(o[nj2][0] * inv0, o[nj2][1] * inv0);
        *(__half2*)(Oatt + (size_t)(b*TSEQ + r1g) * DIM + col) =
            __floats2half2_rn(o[nj2][2] * inv1, o[nj2][3] * inv1);
    }
}

// ---------------- launch ------------------------------------------------------
extern "C" void kernel_launch(void* const* d_in, const int* in_sizes, int n_in,
                              void* d_out, int out_size) {
    const float* x      = (const float*)d_in[0];
    const float* w_qkv  = (const float*)d_in[1];
    const float* w_proj = (const float*)d_in[2];
    float* out = (float*)d_out;

    float *ct, *st;
    __half *xh, *wqkvh, *wprojh, *qh, *kh, *vh, *vth, *atth;
    cudaGetSymbolAddress((void**)&ct,     g_ctab);
    cudaGetSymbolAddress((void**)&st,     g_stab);
    cudaGetSymbolAddress((void**)&xh,     g_xh);
    cudaGetSymbolAddress((void**)&wqkvh,  g_wqkvh);
    cudaGetSymbolAddress((void**)&wprojh, g_wprojh);
    cudaGetSymbolAddress((void**)&qh,     g_qh);
    cudaGetSymbolAddress((void**)&kh,     g_kh);
    cudaGetSymbolAddress((void**)&vh,     g_vh);
    cudaGetSymbolAddress((void**)&vth,    g_vth);
    cudaGetSymbolAddress((void**)&atth,   g_atth);

    cudaFuncSetAttribute(gemm_qkv, cudaFuncAttributeMaxDynamicSharedMemorySize, GEMMH_SMEM);
    cudaFuncSetAttribute(gemm_h,   cudaFuncAttributeMaxDynamicSharedMemorySize, GEMMH_SMEM);
    cudaFuncSetAttribute(flash_h,  cudaFuncAttributeMaxDynamicSharedMemorySize, FLASHH_BYTES);

    build_tab<<<TSEQ, HD>>>(ct, st);

    round_half<<<(M1*(size_t)DIM)/(256*8), 256>>>(x, xh);
    round_half<<<((size_t)N_QKV*DIM)/(256*8), 256>>>(w_qkv, wqkvh);
    round_half<<<((size_t)DIM*DIM)/(256*8), 256>>>(w_proj, wprojh);

    gemm_qkv<<<dim3(N_QKV/BN, M1/BM), 128, GEMMH_SMEM>>>(xh, wqkvh, ct, st, qh, kh, vh);

    vtrans<<<dim3(TSEQ/32, HD/32, BATCH*NH), dim3(32, 8)>>>(vh, vth);

    flash_h<<<dim3(TSEQ/FQ, BATCH*NH), 256, FLASHH_BYTES>>>(qh, kh, vth, atth);

    gemm_h<<<dim3(DIM/BN, M1/BM), 128, GEMMH_SMEM>>>(atth, wprojh, out, DIM, DIM);
}

// round 17
// speedup vs baseline: 1.0198x; 1.0198x over previous
#include <cuda_runtime.h>
#include <cuda_fp16.h>
#include <math.h>
#include <stdint.h>

// Problem constants
#define BATCH 2
#define TSEQ  4096
#define DIM   2048
#define NH    16
#define HD    128
#define M1    (BATCH*TSEQ)      // 8192
#define N_QKV (3*DIM)           // 6144

// ---------------- scratch (static device globals; no allocs allowed) ----------
__device__ float  g_qkv[(size_t)M1 * N_QKV];           // fp32 qkv (GEMM1 out)
__device__ __half g_xh[(size_t)M1 * DIM];
__device__ __half g_wqkvh[(size_t)N_QKV * DIM];
__device__ __half g_wprojh[(size_t)DIM * DIM];
__device__ __half g_qh[(size_t)BATCH*NH*TSEQ*HD];      // [bh][t][d]
__device__ __half g_kh[(size_t)BATCH*NH*TSEQ*HD];      // [bh][t][d]
__device__ __half g_vh[(size_t)BATCH*NH*TSEQ*HD];      // [bh][t][d]
__device__ __half g_atth[(size_t)M1 * DIM];
__device__ float  g_ctab[(size_t)TSEQ * HD];
__device__ float  g_stab[(size_t)TSEQ * HD];

// ---------------- helpers -----------------------------------------------------
__device__ __forceinline__ void mma_f16(float* d, const uint32_t* a, const uint32_t* b) {
    asm volatile(
        "mma.sync.aligned.m16n8k16.row.col.f32.f16.f16.f32 "
        "{%0,%1,%2,%3}, {%4,%5,%6,%7}, {%8,%9}, {%0,%1,%2,%3};"
        : "+f"(d[0]), "+f"(d[1]), "+f"(d[2]), "+f"(d[3])
        : "r"(a[0]), "r"(a[1]), "r"(a[2]), "r"(a[3]), "r"(b[0]), "r"(b[1]));
}

__device__ __forceinline__ void ldsm_x4(uint32_t* r, uint32_t saddr) {
    asm volatile("ldmatrix.sync.aligned.m8n8.x4.shared.b16 {%0,%1,%2,%3}, [%4];"
        : "=r"(r[0]), "=r"(r[1]), "=r"(r[2]), "=r"(r[3]) : "r"(saddr));
}

__device__ __forceinline__ void ldsm_x4_t(uint32_t* r, uint32_t saddr) {
    asm volatile("ldmatrix.sync.aligned.m8n8.x4.trans.shared.b16 {%0,%1,%2,%3}, [%4];"
        : "=r"(r[0]), "=r"(r[1]), "=r"(r[2]), "=r"(r[3]) : "r"(saddr));
}

__device__ __forceinline__ uint32_t smem_u32(const void* p) {
    uint32_t a;
    asm("{ .reg .u64 t; cvta.to.shared.u64 t, %1; cvt.u32.u64 %0, t; }" : "=r"(a) : "l"(p));
    return a;
}
__device__ __forceinline__ void cp_async16(uint32_t saddr, const void* gaddr) {
    asm volatile("cp.async.cg.shared.global [%0], [%1], 16;" :: "r"(saddr), "l"(gaddr));
}
#define CP_COMMIT() asm volatile("cp.async.commit_group;" ::: "memory")
#define CP_WAIT1()  asm volatile("cp.async.wait_group 1;" ::: "memory")
#define CP_WAIT2()  asm volatile("cp.async.wait_group 2;" ::: "memory")

__device__ __forceinline__ uint32_t h2u(__half2 h) {
    union { __half2 h; uint32_t u; } c; c.h = h; return c.u;
}

// ---------------- cos/sin table ----------------------------------------------
__global__ void build_tab(float* __restrict__ ct, float* __restrict__ st) {
    int t = blockIdx.x;
    int j = threadIdx.x;
    int m = j & 63;
    float base = (float)pow(10000.0, (double)m / 64.0);
    float invf = 1.0f / base;
    float ang = (float)t * invf;
    ct[t*HD + j] = cosf(ang);
    st[t*HD + j] = sinf(ang);
}

// ---------------- fp32 -> fp16 pass (8 elems/thread) --------------------------
__global__ void round_half(const float* __restrict__ in, __half* __restrict__ out) {
    size_t i = ((size_t)blockIdx.x * 256 + threadIdx.x) * 8;
    float4 v0 = *(const float4*)(in + i);
    float4 v1 = *(const float4*)(in + i + 4);
    uint4 u;
    u.x = h2u(__floats2half2_rn(v0.x, v0.y));
    u.y = h2u(__floats2half2_rn(v0.z, v0.w));
    u.z = h2u(__floats2half2_rn(v1.x, v1.y));
    u.w = h2u(__floats2half2_rn(v1.z, v1.w));
    *(uint4*)(out + i) = u;
}

// ---------------- fp16 cp.async pipelined GEMM: C = A * B^T -------------------
// 128x128 CTA tile, 4 warps (2x2) of 64x64, BK=32, 4 stages, 128 threads.
#define BM 128
#define BN 128
#define BKH 32
#define STAGES 4
#define HSTR 40
#define GEMMH_SMEM (STAGES * (BM + BN) * HSTR * 2)    // 81920 B

__global__ __launch_bounds__(128, 2) void gemm_h(
    const __half* __restrict__ A, const __half* __restrict__ B,
    float* __restrict__ C, int M, int N, int K)
{
    extern __shared__ __half hsm[];
    uint32_t sbase = smem_u32(hsm);
    const uint32_t boff = STAGES * BM * HSTR;          // halves

    int tid  = threadIdx.x;
    int wid  = tid >> 5, lane = tid & 31;
    int g    = lane >> 2, tg = lane & 3;
    int wm   = wid >> 1, wn = wid & 1;
    int m0   = blockIdx.y * BM;
    int n0   = blockIdx.x * BN;

    int la_row = lane & 15;
    int la_k   = (lane >> 4) << 3;
    int lb_row = ((lane >> 4) << 3) + (lane & 7);
    int lb_k   = ((lane >> 3) & 1) << 3;

    float acc[4][8][4];
#pragma unroll
    for (int i = 0; i < 4; i++)
#pragma unroll
        for (int j = 0; j < 8; j++)
#pragma unroll
            for (int r = 0; r < 4; r++) acc[i][j][r] = 0.f;

    const int nch = K / BKH;

    auto issue = [&](int ch, bool pred) {
        if (pred) {
            int s = ch % STAGES;
            const __half* Ag = A + (size_t)m0 * K + ch * BKH;
            const __half* Bg = B + (size_t)n0 * K + ch * BKH;
            uint32_t as = sbase + (uint32_t)(s * BM * HSTR) * 2u;
            uint32_t bs = sbase + (boff + (uint32_t)(s * BN * HSTR)) * 2u;
#pragma unroll
            for (int e = 0; e < 4; e++) {
                int idx = tid + e * 128;
                int r  = idx >> 2;
                int c8 = (idx & 3) << 3;
                cp_async16(as + (uint32_t)(r * HSTR + c8) * 2u, Ag + (size_t)r * K + c8);
                cp_async16(bs + (uint32_t)(r * HSTR + c8) * 2u, Bg + (size_t)r * K + c8);
            }
        }
        CP_COMMIT();
    };

    issue(0, true);
    issue(1, 1 < nch);
    issue(2, 2 < nch);

    for (int ch = 0; ch < nch; ch++) {
        CP_WAIT2();
        __syncthreads();
        issue(ch + 3, ch + 3 < nch);

        int s = ch % STAGES;
        uint32_t asad = sbase + (uint32_t)(s * BM * HSTR) * 2u;
        uint32_t bsad = sbase + (boff + (uint32_t)(s * BN * HSTR)) * 2u;

#pragma unroll
        for (int ks = 0; ks < BKH; ks += 16) {
            uint32_t afr[4][4];
#pragma unroll
            for (int mi = 0; mi < 4; mi++) {
                int mr = wm * 64 + mi * 16;
                ldsm_x4(afr[mi], asad + (uint32_t)((mr + la_row) * HSTR + ks + la_k) * 2u);
            }
            uint32_t bfr[8][2];
#pragma unroll
            for (int p = 0; p < 4; p++) {
                int nr2 = wn * 64 + p * 16;
                uint32_t r4[4];
                ldsm_x4(r4, bsad + (uint32_t)((nr2 + lb_row) * HSTR + ks + lb_k) * 2u);
                bfr[2*p  ][0] = r4[0]; bfr[2*p  ][1] = r4[1];
                bfr[2*p+1][0] = r4[2]; bfr[2*p+1][1] = r4[3];
            }
#pragma unroll
            for (int mi = 0; mi < 4; mi++)
#pragma unroll
                for (int nj = 0; nj < 8; nj++)
                    mma_f16(acc[mi][nj], afr[mi], bfr[nj]);
        }
    }

#pragma unroll
    for (int mi = 0; mi < 4; mi++) {
#pragma unroll
        for (int nj = 0; nj < 8; nj++) {
            int row = m0 + wm * 64 + mi * 16 + g;
            int col = n0 + wn * 64 + nj * 8 + tg * 2;
            *(float2*)(C + (size_t)row * N + col) =
                make_float2(acc[mi][nj][0], acc[mi][nj][1]);
            *(float2*)(C + (size_t)(row + 8) * N + col) =
                make_float2(acc[mi][nj][2], acc[mi][nj][3]);
        }
    }
}

// ---------------- RoPE + head split -> half Q,K,V ----------------------------
// One block per token; c/s loaded once, reused over 4 heads per thread.
__global__ void rope_split(const float* __restrict__ qkv,
                           const float* __restrict__ ct, const float* __restrict__ st,
                           __half* __restrict__ Qo, __half* __restrict__ Ko,
                           __half* __restrict__ Vo)
{
    int bt  = blockIdx.x;
    int tid = threadIdx.x;           // 256
    int j2  = tid & 63;
    int hh  = tid >> 6;
    int b   = bt >> 12;
    int t   = bt & (TSEQ - 1);
    int j   = 2 * j2;

    float2 c = *(const float2*)(ct + t*HD + j);
    float2 s = *(const float2*)(st + t*HD + j);

#pragma unroll
    for (int e = 0; e < 4; e++) {
        int h = hh + e * 4;
        size_t base = (size_t)bt * N_QKV + h * HD + j;
        float2 xq = *(const float2*)(qkv + base);
        float2 xk = *(const float2*)(qkv + base + DIM);
        float2 xv = *(const float2*)(qkv + base + 2*DIM);
        float oq0 = xq.x * c.x - xq.y * s.x;
        float oq1 = xq.y * c.y + xq.x * s.y;
        float ok0 = xk.x * c.x - xk.y * s.x;
        float ok1 = xk.y * c.y + xk.x * s.y;
        size_t ob = ((size_t)(b*NH + h) * TSEQ + t) * HD + j;
        *(__half2*)(Qo + ob) = __floats2half2_rn(oq0, oq1);
        *(__half2*)(Ko + ob) = __floats2half2_rn(ok0, ok1);
        *(__half2*)(Vo + ob) = __floats2half2_rn(xv.x, xv.y);
    }
}

// ---------------- fp16 mma flash attention (causal, FK=128, trans-V) ---------
// Q tile 128, K tile 128, 8 warps; warp = 16 Q rows x full K width.
// V kept [t][d] in smem; PV B-fragments via ldmatrix.trans.
#define FQ 128
#define FK 128
#define QSTR 136       // halves
#define KSTR 136
#define VSTR 136
#define PSTR 136
#define OFF_Q  0
#define OFF_K0 (OFF_Q  + FQ*QSTR)     // 17408
#define OFF_K1 (OFF_K0 + FK*KSTR)     // 34816
#define OFF_V  (OFF_K1 + FK*KSTR)     // 52224
#define OFF_P  (OFF_V  + FK*VSTR)     // 69632
#define FLASHH_HALVES (OFF_P + FQ*PSTR)   // 87040
#define FLASHH_BYTES (FLASHH_HALVES * 2)  // 174080

__global__ __launch_bounds__(256, 1) void flash_h(
    const __half* __restrict__ Q, const __half* __restrict__ K,
    const __half* __restrict__ V, __half* __restrict__ Oatt)
{
    extern __shared__ __half hs[];
    __half* Ps = hs + OFF_P;
    uint32_t sbase = smem_u32(hs);

    int qi  = gridDim.x - 1 - blockIdx.x;   // LPT: longest CTAs first
    int bh  = blockIdx.y;
    int tid = threadIdx.x;
    int w    = tid >> 5;
    int lane = tid & 31;
    int g    = lane >> 2;
    int tg   = lane & 3;

    int la_row = lane & 15;
    int la_k   = (lane >> 4) << 3;
    int lb_row = ((lane >> 4) << 3) + (lane & 7);
    int lb_k   = ((lane >> 3) & 1) << 3;
    // trans-V lane map: t within 16-row group, d-base 0/8
    int lv_t = ((lane >> 3) & 1) * 8 + (lane & 7);
    int lv_d = (lane >> 4) << 3;

    const __half* Qp = Q + (size_t)bh * TSEQ * HD;
    const __half* Kp = K + (size_t)bh * TSEQ * HD;
    const __half* Vp = V + (size_t)bh * TSEQ * HD;

    int q0 = qi * FQ;
    int nkt = qi + 1;

    auto issueK = [&](int kt, bool pred) {
        if (pred) {
            int k0 = kt * FK;
            uint32_t kb = sbase + (uint32_t)((kt & 1) ? OFF_K1 : OFF_K0) * 2u;
#pragma unroll
            for (int e = 0; e < 8; e++) {
                int idx = tid + e * 256;
                int r  = idx >> 4;
                int c8 = (idx & 15) << 3;
                cp_async16(kb + (uint32_t)(r * KSTR + c8) * 2u,
                           Kp + (size_t)(k0 + r) * HD + c8);
            }
        }
        CP_COMMIT();
    };
    auto issueV = [&](int kt) {
        int k0 = kt * FK;
        uint32_t vb = sbase + (uint32_t)OFF_V * 2u;
#pragma unroll
        for (int e = 0; e < 8; e++) {
            int idx = tid + e * 256;
            int r  = idx >> 4;
            int c8 = (idx & 15) << 3;
            cp_async16(vb + (uint32_t)(r * VSTR + c8) * 2u,
                       Vp + (size_t)(k0 + r) * HD + c8);
        }
        CP_COMMIT();
    };

    issueK(0, true);

    // load Q tile
#pragma unroll
    for (int e = 0; e < 8; e++) {
        int idx = tid + e * 256;
        int r  = idx >> 4;
        int c8 = (idx & 15) << 3;
        uint4 v = *(const uint4*)(Qp + (size_t)(q0 + r) * HD + c8);
        *(uint4*)(hs + OFF_Q + r * QSTR + c8) = v;
    }

    float o[16][4];
#pragma unroll
    for (int i = 0; i < 16; i++)
#pragma unroll
        for (int j = 0; j < 4; j++) o[i][j] = 0.f;

    float m0r = -1e30f, m1r = -1e30f;
    float l0 = 0.f, l1 = 0.f;
    const float scale = 0.08838834764831845f;   // 1/sqrt(128)

    int rowbase = q0 + w * 16;
    int r0g = rowbase + g;
    int r1g = rowbase + g + 8;
    int rq = rowbase - q0;

    uint32_t qad   = sbase + (uint32_t)(OFF_Q + (rq + la_row) * QSTR + la_k) * 2u;
    uint32_t pad_a = sbase + (uint32_t)(OFF_P + (rq + la_row) * PSTR + la_k) * 2u;
    uint32_t vad0  = sbase + (uint32_t)(OFF_V + lv_t * VSTR + lv_d) * 2u;

    float s[16][4];

    for (int kt = 0; kt < nkt; kt++) {
        int k0 = kt * FK;
        uint32_t kad = sbase + (uint32_t)(((kt & 1) ? OFF_K1 : OFF_K0) + lb_row * KSTR + lb_k) * 2u;

        issueV(kt);
        issueK(kt + 1, kt + 1 < nkt);
        CP_WAIT2();                 // K(kt) done; V(kt), K(kt+1) in flight
        __syncthreads();

        // ---- S = Q K^T : 8 ks steps of k=16, 16 column tiles ----
#pragma unroll
        for (int nj = 0; nj < 16; nj++)
#pragma unroll
            for (int r = 0; r < 4; r++) s[nj][r] = 0.f;

#pragma unroll
        for (int ks = 0; ks < 8; ks++) {
            uint32_t a[4];
            ldsm_x4(a, qad + (uint32_t)(ks * 16) * 2u);
            uint32_t bfr[16][2];
#pragma unroll
            for (int p = 0; p < 8; p++) {
                uint32_t r4[4];
                ldsm_x4(r4, kad + (uint32_t)(p * 16 * KSTR + ks * 16) * 2u);
                bfr[2*p  ][0] = r4[0]; bfr[2*p  ][1] = r4[1];
                bfr[2*p+1][0] = r4[2]; bfr[2*p+1][1] = r4[3];
            }
#pragma unroll
            for (int nj = 0; nj < 16; nj++)
                mma_f16(s[nj], a, bfr[nj]);
        }

        // ---- causal mask (only the diagonal tile) ----
        if (k0 + FK - 1 > rowbase) {
#pragma unroll
            for (int nj = 0; nj < 16; nj++) {
                int c = k0 + nj*8 + 2*tg;
                if (c     > r0g) s[nj][0] = -1e30f;
                if (c + 1 > r0g) s[nj][1] = -1e30f;
                if (c     > r1g) s[nj][2] = -1e30f;
                if (c + 1 > r1g) s[nj][3] = -1e30f;
            }
        }

        // ---- online softmax (warp-local, quad reductions) ----
        float mx0 = -1e30f, mx1 = -1e30f;
#pragma unroll
        for (int nj = 0; nj < 16; nj++) {
            mx0 = fmaxf(mx0, fmaxf(s[nj][0], s[nj][1]));
            mx1 = fmaxf(mx1, fmaxf(s[nj][2], s[nj][3]));
        }
        mx0 = fmaxf(mx0, __shfl_xor_sync(0xffffffff, mx0, 1));
        mx0 = fmaxf(mx0, __shfl_xor_sync(0xffffffff, mx0, 2));
        mx1 = fmaxf(mx1, __shfl_xor_sync(0xffffffff, mx1, 1));
        mx1 = fmaxf(mx1, __shfl_xor_sync(0xffffffff, mx1, 2));

        float mn0 = fmaxf(m0r, mx0);
        float mn1 = fmaxf(m1r, mx1);
        float al0 = __expf((m0r - mn0) * scale);
        float al1 = __expf((m1r - mn1) * scale);
        m0r = mn0; m1r = mn1;

        float sum0 = 0.f, sum1 = 0.f;
#pragma unroll
        for (int nj = 0; nj < 16; nj++) {
            float p0 = __expf((s[nj][0] - mn0) * scale);
            float p1 = __expf((s[nj][1] - mn0) * scale);
            float p2 = __expf((s[nj][2] - mn1) * scale);
            float p3 = __expf((s[nj][3] - mn1) * scale);
            s[nj][0] = p0; s[nj][1] = p1; s[nj][2] = p2; s[nj][3] = p3;
            sum0 += p0 + p1; sum1 += p2 + p3;
        }
        sum0 += __shfl_xor_sync(0xffffffff, sum0, 1);
        sum0 += __shfl_xor_sync(0xffffffff, sum0, 2);
        sum1 += __shfl_xor_sync(0xffffffff, sum1, 1);
        sum1 += __shfl_xor_sync(0xffffffff, sum1, 2);

        l0 = l0 * al0 + sum0;
        l1 = l1 * al1 + sum1;

#pragma unroll
        for (int t2 = 0; t2 < 16; t2++) {
            o[t2][0] *= al0; o[t2][1] *= al0;
            o[t2][2] *= al1; o[t2][3] *= al1;
        }

        // ---- write P (half2 pairs) ----
        int pr0 = (rq + g) * PSTR;
        int pr1 = (rq + g + 8) * PSTR;
#pragma unroll
        for (int nj = 0; nj < 16; nj++) {
            int c = nj*8 + 2*tg;
            *(__half2*)(Ps + pr0 + c) = __floats2half2_rn(s[nj][0], s[nj][1]);
            *(__half2*)(Ps + pr1 + c) = __floats2half2_rn(s[nj][2], s[nj][3]);
        }

        CP_WAIT1();                 // V(kt) done; K(kt+1) may be in flight
        __syncthreads();

        // ---- O += P V : 8 ks2 steps of k=16 tokens, 16 d-tiles (trans-V) ----
#pragma unroll
        for (int ks2 = 0; ks2 < 8; ks2++) {
            uint32_t a2[4];
            ldsm_x4(a2, pad_a + (uint32_t)(ks2 * 16) * 2u);
            uint32_t vrow = vad0 + (uint32_t)(ks2 * 16 * VSTR) * 2u;
#pragma unroll
            for (int p = 0; p < 8; p++) {
                uint32_t r4[4];
                ldsm_x4_t(r4, vrow + (uint32_t)(p * 16) * 2u);
                uint32_t b0[2] = { r4[0], r4[1] };
                uint32_t b1[2] = { r4[2], r4[3] };
                mma_f16(o[2*p  ], a2, b0);
                mma_f16(o[2*p+1], a2, b1);
            }
        }
        __syncthreads();            // V buffer + K stage free for next iter
    }

    // epilogue: normalize + write att as half (proj GEMM A operand)
    float inv0 = 1.0f / l0;
    float inv1 = 1.0f / l1;
    int b = bh >> 4, h = bh & 15;
#pragma unroll
    for (int nj2 = 0; nj2 < 16; nj2++) {
        int col = h * HD + nj2*8 + 2*tg;
        *(__half2*)(Oatt + (size_t)(b*TSEQ + r0g) * DIM + col) =
            __floats2half2_rn(o[nj2][0] * inv0, o[nj2][1] * inv0);
        *(__half2*)(Oatt + (size_t)(b*TSEQ + r1g) * DIM + col) =
            __floats2half2_rn(o[nj2][2] * inv1, o[nj2][3] * inv1);
    }
}

// ---------------- launch ------------------------------------------------------
extern "C" void kernel_launch(void* const* d_in, const int* in_sizes, int n_in,
                              void* d_out, int out_size) {
    const float* x      = (const float*)d_in[0];
    const float* w_qkv  = (const float*)d_in[1];
    const float* w_proj = (const float*)d_in[2];
    float* out = (float*)d_out;

    float *qkv, *ct, *st;
    __half *xh, *wqkvh, *wprojh, *qh, *kh, *vh, *atth;
    cudaGetSymbolAddress((void**)&qkv,    g_qkv);
    cudaGetSymbolAddress((void**)&ct,     g_ctab);
    cudaGetSymbolAddress((void**)&st,     g_stab);
    cudaGetSymbolAddress((void**)&xh,     g_xh);
    cudaGetSymbolAddress((void**)&wqkvh,  g_wqkvh);
    cudaGetSymbolAddress((void**)&wprojh, g_wprojh);
    cudaGetSymbolAddress((void**)&qh,     g_qh);
    cudaGetSymbolAddress((void**)&kh,     g_kh);
    cudaGetSymbolAddress((void**)&vh,     g_vh);
    cudaGetSymbolAddress((void**)&atth,   g_atth);

    cudaFuncSetAttribute(gemm_h,  cudaFuncAttributeMaxDynamicSharedMemorySize, GEMMH_SMEM);
    cudaFuncSetAttribute(flash_h, cudaFuncAttributeMaxDynamicSharedMemorySize, FLASHH_BYTES);

    build_tab<<<TSEQ, HD>>>(ct, st);

    round_half<<<(M1*(size_t)DIM)/(256*8), 256>>>(x, xh);
    round_half<<<((size_t)N_QKV*DIM)/(256*8), 256>>>(w_qkv, wqkvh);
    round_half<<<((size_t)DIM*DIM)/(256*8), 256>>>(w_proj, wprojh);

    gemm_h<<<dim3(N_QKV/BN, M1/BM), 128, GEMMH_SMEM>>>(xh, wqkvh, qkv, M1, N_QKV, DIM);

    rope_split<<<M1, 256>>>(qkv, ct, st, qh, kh, vh);

    flash_h<<<dim3(TSEQ/FQ, BATCH*NH), 256, FLASHH_BYTES>>>(qh, kh, vh, atth);

    gemm_h<<<dim3(DIM/BN, M1/BM), 128, GEMMH_SMEM>>>(atth, wprojh, out, M1, DIM, DIM);
}